// round 15
// baseline (speedup 1.0000x reference)
#include <cuda_runtime.h>
#include <cuda_bf16.h>
#include <cuda_fp16.h>
#include <math.h>
#include <stdint.h>

#define NMAX   20000
#define EMAX   320000
#define DIN    512
#define D      256
#define NREL   6
#define NTYPE  8
#define KREL   (NREL * D)         // 1536
#define KTOT   (KREL + D)         // 1792
#define NCH2   (KTOT / 32)        // 56
#define NCHA   (DIN / 32)         // 16

// ---------------- scratch ----------------
__device__ float g_h2 [NMAX * D];
__device__ float g_inv[NMAX];
__device__ int   g_deg[NMAX];
__device__ int   g_cnt[NTYPE];
__device__ int   g_off[NTYPE + 1];
__device__ int   g_cur[NTYPE];
__device__ int   g_order[NMAX];
__device__ int   g_roff[NMAX + 1];
__device__ int   g_rcur[NMAX];
__device__ int   g_epack[EMAX];            // src*8 + rel
// A for layer GEMMs: single fp16 [m][KTOT]  (h-part doubles as fp16 h storage)
__device__ __half g_Af[(size_t)NMAX * KTOT];
// B for layer GEMMs: single fp16 [layer][n][k]
__device__ __half g_Bf[2 * 256 * KTOT];
// adapt path: single fp16 X and W
__device__ __half g_Xf[(size_t)NMAX * DIN];
__device__ __half g_Waf[NTYPE * D * DIN];

// ---------------- helpers ----------------
__device__ __forceinline__ uint32_t smem_u32(const void* p) {
    uint32_t a;
    asm("{ .reg .u64 t; cvta.to.shared.u64 t, %1; cvt.u32.u64 %0, t; }" : "=r"(a) : "l"(p));
    return a;
}
__device__ __forceinline__ void mma_f16(float* c, const uint32_t* a, uint32_t b0, uint32_t b1) {
    asm volatile(
        "mma.sync.aligned.m16n8k16.row.col.f32.f16.f16.f32 "
        "{%0,%1,%2,%3}, {%4,%5,%6,%7}, {%8,%9}, {%0,%1,%2,%3};"
        : "+f"(c[0]), "+f"(c[1]), "+f"(c[2]), "+f"(c[3])
        : "r"(a[0]), "r"(a[1]), "r"(a[2]), "r"(a[3]), "r"(b0), "r"(b1));
}
__device__ __forceinline__ void ldsm4(uint32_t* r, uint32_t addr) {
    asm volatile("ldmatrix.sync.aligned.m8n8.x4.shared.b16 {%0,%1,%2,%3}, [%4];"
                 : "=r"(r[0]), "=r"(r[1]), "=r"(r[2]), "=r"(r[3]) : "r"(addr));
}
#define CP_ASYNC16(dst, src) \
    asm volatile("cp.async.cg.shared.global [%0], [%1], 16;" :: "r"(dst), "l"(src) : "memory")
#define CP_COMMIT()  asm volatile("cp.async.commit_group;" ::: "memory")
#define CP_WAIT1()   asm volatile("cp.async.wait_group 1;" ::: "memory")
#define CP_WAIT0()   asm volatile("cp.async.wait_group 0;" ::: "memory")

__device__ __forceinline__ uint32_t pack_h2(float x, float y) {
    __half2 h = __floats2half2_rn(x, y);
    return *reinterpret_cast<uint32_t*>(&h);
}

// ---------------- small prep kernels ----------------
__global__ void k_init(int Nn) {
    int i = blockIdx.x * 256 + threadIdx.x;
    if (i < Nn)    g_deg[i] = 0;
    if (i < NTYPE) g_cnt[i] = 0;
}
__global__ void k_count(const int* __restrict__ ei, int E_) {
    int e = blockIdx.x * 256 + threadIdx.x;
    if (e < E_) atomicAdd(&g_deg[ei[E_ + e]], 1);
}
__global__ void k_hist(const int* __restrict__ nt, int Nn) {
    int i = blockIdx.x * 256 + threadIdx.x;
    if (i < Nn) atomicAdd(&g_cnt[nt[i]], 1);
}
__global__ void k_inv(int Nn) {
    int i = blockIdx.x * 256 + threadIdx.x;
    if (i < Nn) g_inv[i] = 1.0f / fmaxf((float)g_deg[i], 1.0f);
}
__global__ void k_offs() {
    int s = 0;
    for (int t = 0; t < NTYPE; t++) { g_off[t] = s; g_cur[t] = s; s += g_cnt[t]; }
    g_off[NTYPE] = s;
}
__global__ void k_order(const int* __restrict__ nt, int Nn) {
    int i = blockIdx.x * 256 + threadIdx.x;
    if (i < Nn) {
        int pos = atomicAdd(&g_cur[nt[i]], 1);
        g_order[pos] = i;
    }
}
__global__ void k_prefix(int Nn, int E_) {
    __shared__ int sums[1024];
    int tid = threadIdx.x;
    int per = (Nn + 1023) / 1024;
    int base = tid * per;
    int s = 0;
    for (int i = 0; i < per; i++) {
        int idx = base + i;
        if (idx < Nn) s += g_deg[idx];
    }
    sums[tid] = s;
    __syncthreads();
    if (tid == 0) {
        int acc = 0;
        for (int i = 0; i < 1024; i++) { int t = sums[i]; sums[i] = acc; acc += t; }
    }
    __syncthreads();
    int run = sums[tid];
    for (int i = 0; i < per; i++) {
        int idx = base + i;
        if (idx < Nn) {
            g_roff[idx] = run;
            g_rcur[idx] = run;
            run += g_deg[idx];
        }
    }
    if (tid == 0) g_roff[Nn] = E_;
}
__global__ void k_fillcsr(const int* __restrict__ ei, const int* __restrict__ et, int E_) {
    int e = blockIdx.x * 256 + threadIdx.x;
    if (e >= E_) return;
    int dst = ei[E_ + e];
    int pos = atomicAdd(&g_rcur[dst], 1);
    g_epack[pos] = ei[e] * 8 + et[e];
}
// pack B single fp16, transposed to [l][e][k]
__global__ void k_packB(const float* __restrict__ Wrel, const float* __restrict__ Wself) {
    int idx = blockIdx.x * 256 + threadIdx.x;
    if (idx >= 2 * 256 * KTOT) return;
    int l    = idx / (256 * KTOT);
    int rest = idx % (256 * KTOT);
    int e    = rest / KTOT;
    int k    = rest % KTOT;
    float w;
    if (k < KREL) w = Wrel[(((size_t)l * NREL + (k >> 8)) * D + (k & 255)) * D + e];
    else          w = Wself[((size_t)l * D + (k - KREL)) * D + e];
    g_Bf[idx] = __float2half_rn(w);
}
__global__ void k_packWa(const float* __restrict__ W) {
    int idx = blockIdx.x * 256 + threadIdx.x;
    if (idx >= NTYPE * D * DIN) return;
    g_Waf[idx] = __float2half_rn(W[idx]);
}
__global__ void k_convX(const float* __restrict__ X, int Nn) {
    int i4 = blockIdx.x * 256 + threadIdx.x;
    if (i4 >= Nn * (DIN / 4)) return;
    int k = i4 * 4;
    float4 v = *(const float4*)&X[(size_t)k];
    *(uint2*)&g_Xf[(size_t)k] = make_uint2(pack_h2(v.x, v.y), pack_h2(v.z, v.w));
}
// h fp32 -> fp16 into h-part of A (race-free: own launch)
__global__ void k_convH(const float* __restrict__ hin, int Nn) {
    int i = blockIdx.x * 256 + threadIdx.x;
    if (i >= Nn * (D / 4)) return;
    int m = i >> 6;
    int k = (i & 63) * 4;
    float4 v = *(const float4*)&hin[(size_t)m * D + k];
    size_t off = (size_t)m * KTOT + KREL + k;
    *(uint2*)&g_Af[off] = make_uint2(pack_h2(v.x, v.y), pack_h2(v.z, v.w));
}

// ---------------- CSR gather-aggregate: fp16 gathers from g_Af h-part --------
// h-part of g_Af is written (adapt epilogue for l=0, k_convH for l=1) strictly
// before this launch; this kernel reads h-part and writes rel-part (disjoint).
__global__ void k_aggregate(int Nn) {
    int gw   = (blockIdx.x * blockDim.x + threadIdx.x) >> 5;
    int lane = threadIdx.x & 31;
    if (gw >= Nn) return;
    int start = g_roff[gw], end = g_roff[gw + 1];
    float acc[NREL][8];
#pragma unroll
    for (int r = 0; r < NREL; r++)
#pragma unroll
        for (int j = 0; j < 8; j++) acc[r][j] = 0.f;

    for (int i = start; i < end; i++) {
        int p = g_epack[i];
        int s = p >> 3, r = p & 7;
        uint4 hv = *(const uint4*)(g_Af + (size_t)s * KTOT + KREL + lane * 8);
        const __half2* hp = (const __half2*)&hv;
        float2 f0 = __half22float2(hp[0]);
        float2 f1 = __half22float2(hp[1]);
        float2 f2 = __half22float2(hp[2]);
        float2 f3 = __half22float2(hp[3]);
        float v[8] = {f0.x, f0.y, f1.x, f1.y, f2.x, f2.y, f3.x, f3.y};
#pragma unroll
        for (int rr = 0; rr < NREL; rr++) {
            if (rr == r) {
#pragma unroll
                for (int j = 0; j < 8; j++) acc[rr][j] += v[j];
            }
        }
    }
    float s = g_inv[gw];
#pragma unroll
    for (int r = 0; r < NREL; r++) {
        uint32_t hw[4];
#pragma unroll
        for (int q = 0; q < 4; q++)
            hw[q] = pack_h2(acc[r][2 * q] * s, acc[r][2 * q + 1] * s);
        size_t off = (size_t)gw * KTOT + r * D + lane * 8;
        *(uint4*)&g_Af[off] = make_uint4(hw[0], hw[1], hw[2], hw[3]);
    }
}

// ---------------- adapt GEMM via mma: single-product f16 ---------------------
#define ADA_A  0
#define ADA_B  10240
#define ADA_BUF 30720
#define ADA_SMEM (2 * ADA_BUF)   // 61440

__global__ __launch_bounds__(256, 2)
void adapt_mma(const float* __restrict__ bias, int Nn) {
    extern __shared__ char smem[];
    __shared__ int nid_s[128];
    uint32_t sb = smem_u32(smem);
    int t    = blockIdx.y;
    int base = g_off[t];
    int cntv = g_off[t + 1] - base;
    int m0   = blockIdx.x * 128;
    if (m0 >= cntv) return;

    int tid  = threadIdx.x;
    int wid  = tid >> 5;
    int lane = tid & 31;
    int wm   = wid & 3;
    int wn   = wid >> 2;

    if (tid < 128) {
        int idx = m0 + tid;
        nid_s[tid] = (idx < cntv) ? g_order[base + idx] : g_order[base];
    }
    __syncthreads();

    const __half* Wf = g_Waf + (size_t)t * D * DIN;

    float acc[2][16][4];
#pragma unroll
    for (int i = 0; i < 2; i++)
#pragma unroll
        for (int j = 0; j < 16; j++)
#pragma unroll
            for (int q = 0; q < 4; q++) acc[i][j][q] = 0.f;

    auto load_chunk = [&](int c, int p) {
        int k0 = c * 32;
        uint32_t dstb = sb + p * ADA_BUF;
#pragma unroll
        for (int i = 0; i < 6; i++) {
            int sid = tid + i * 256;
            const __half* srcp;
            uint32_t dst;
            if (sid < 512) {
                int row = sid >> 2, seg = sid & 3;
                srcp = g_Xf + (size_t)nid_s[row] * DIN + k0 + seg * 8;
                dst  = dstb + ADA_A + row * 80 + seg * 16;
            } else {
                int t2 = sid - 512;
                int row = t2 >> 2, seg = t2 & 3;
                srcp = Wf + (size_t)row * DIN + k0 + seg * 8;
                dst  = dstb + ADA_B + row * 80 + seg * 16;
            }
            CP_ASYNC16(dst, srcp);
        }
        CP_COMMIT();
    };

    load_chunk(0, 0);
    for (int c = 0; c < NCHA; c++) {
        int p = c & 1;
        if (c + 1 < NCHA) { load_chunk(c + 1, p ^ 1); CP_WAIT1(); }
        else              { CP_WAIT0(); }
        __syncthreads();
        uint32_t bufb = sb + p * ADA_BUF;
#pragma unroll
        for (int ks = 0; ks < 2; ks++) {
            uint32_t ah[2][4];
            int arow = wm * 32 + (lane & 15);
            uint32_t acol = ((uint32_t)((lane >> 4) * 8 + ks * 16)) * 2;
#pragma unroll
            for (int mt = 0; mt < 2; mt++)
                ldsm4(ah[mt], bufb + ADA_A + (arow + mt * 16) * 80 + acol);
            int brow0 = wn * 128 + ((lane >> 4) * 8) + (lane & 7);
            uint32_t bkoff = ((uint32_t)(ks * 16 + ((lane >> 3) & 1) * 8)) * 2;
#pragma unroll
            for (int np = 0; np < 8; np++) {
                uint32_t bh[4];
                ldsm4(bh, bufb + ADA_B + (brow0 + np * 16) * 80 + bkoff);
#pragma unroll
                for (int mt = 0; mt < 2; mt++) {
                    mma_f16(acc[mt][np * 2],     ah[mt], bh[0], bh[1]);
                    mma_f16(acc[mt][np * 2 + 1], ah[mt], bh[2], bh[3]);
                }
            }
        }
        __syncthreads();
    }

    // epilogue: tanh + bias; write fp16 h directly into g_Af h-part
    int g   = lane >> 2;
    int tig = lane & 3;
#pragma unroll
    for (int mt = 0; mt < 2; mt++) {
        int lr0 = wm * 32 + mt * 16 + g;
#pragma unroll
        for (int half = 0; half < 2; half++) {
            int lr = lr0 + half * 8;
            if (m0 + lr >= cntv) continue;
            int node = nid_s[lr];
#pragma unroll
            for (int nt = 0; nt < 16; nt++) {
                int col = wn * 128 + nt * 8 + tig * 2;
                float vx = tanhf(acc[mt][nt][half * 2]     + bias[t * D + col]);
                float vy = tanhf(acc[mt][nt][half * 2 + 1] + bias[t * D + col + 1]);
                *(uint32_t*)&g_Af[(size_t)node * KTOT + KREL + col] = pack_h2(vx, vy);
            }
        }
    }
}

// ---------------- fused layer GEMM: single-product f16, 128x128, 2 CTAs/SM ---
#define G_A  0
#define G_B  10240
#define G_BUF 20480
#define G_SMEM (2 * G_BUF)    // 40960

__global__ __launch_bounds__(256, 2)
void gemm_layer_mma(const float* __restrict__ bself, float* __restrict__ hout,
                    int Nn, int layer) {
    extern __shared__ char smem[];
    uint32_t sb = smem_u32(smem);
    int tid  = threadIdx.x;
    int wid  = tid >> 5;
    int lane = tid & 31;
    int wm   = wid & 3;            // 4 warp rows x 32
    int wn   = wid >> 2;           // 2 warp cols x 64
    int m0   = blockIdx.x * 128;
    int n0   = blockIdx.y * 128;

    const __half* B_g = g_Bf + (size_t)layer * 256 * KTOT + (size_t)n0 * KTOT;

    float acc[2][8][4];
#pragma unroll
    for (int i = 0; i < 2; i++)
#pragma unroll
        for (int j = 0; j < 8; j++)
#pragma unroll
            for (int q = 0; q < 4; q++) acc[i][j][q] = 0.f;

    auto load_chunk = [&](int c, int p) {
        int k0 = c * 32;
        uint32_t dstb = sb + p * G_BUF;
#pragma unroll
        for (int i = 0; i < 4; i++) {
            int sid = tid + i * 256;
            int arr = sid >> 9;            // 0:A 1:B
            int s   = sid & 511;
            int row = s >> 2;
            int seg = s & 3;
            const __half* srcp;
            if (arr == 0) {
                int grow = m0 + row; if (grow > Nn - 1) grow = Nn - 1;
                srcp = g_Af + (size_t)grow * KTOT + k0 + seg * 8;
            } else {
                srcp = B_g + (size_t)row * KTOT + k0 + seg * 8;
            }
            CP_ASYNC16(dstb + arr * 10240 + row * 80 + seg * 16, srcp);
        }
        CP_COMMIT();
    };

    load_chunk(0, 0);
    for (int c = 0; c < NCH2; c++) {
        int p = c & 1;
        if (c + 1 < NCH2) { load_chunk(c + 1, p ^ 1); CP_WAIT1(); }
        else              { CP_WAIT0(); }
        __syncthreads();
        uint32_t bufb = sb + p * G_BUF;
#pragma unroll
        for (int ks = 0; ks < 2; ks++) {
            uint32_t ah[2][4];
            int arow = wm * 32 + (lane & 15);
            uint32_t acol = ((uint32_t)((lane >> 4) * 8 + ks * 16)) * 2;
#pragma unroll
            for (int mt = 0; mt < 2; mt++)
                ldsm4(ah[mt], bufb + G_A + (arow + mt * 16) * 80 + acol);
            int brow0 = wn * 64 + ((lane >> 4) * 8) + (lane & 7);
            uint32_t bkoff = ((uint32_t)(ks * 16 + ((lane >> 3) & 1) * 8)) * 2;
#pragma unroll
            for (int np = 0; np < 4; np++) {
                uint32_t bh[4];
                ldsm4(bh, bufb + G_B + (brow0 + np * 16) * 80 + bkoff);
#pragma unroll
                for (int mt = 0; mt < 2; mt++) {
                    mma_f16(acc[mt][np * 2],     ah[mt], bh[0], bh[1]);
                    mma_f16(acc[mt][np * 2 + 1], ah[mt], bh[2], bh[3]);
                }
            }
        }
        __syncthreads();
    }

    // epilogue: bias + relu
    int g   = lane >> 2;
    int tig = lane & 3;
#pragma unroll
    for (int mt = 0; mt < 2; mt++) {
        int row0 = m0 + wm * 32 + mt * 16 + g;
#pragma unroll
        for (int half = 0; half < 2; half++) {
            int row = row0 + half * 8;
            if (row >= Nn) continue;
#pragma unroll
            for (int nt = 0; nt < 8; nt++) {
                int col = n0 + wn * 64 + nt * 8 + tig * 2;
                float vx = fmaxf(acc[mt][nt][half * 2]     + bself[col], 0.f);
                float vy = fmaxf(acc[mt][nt][half * 2 + 1] + bself[col + 1], 0.f);
                *(float2*)&hout[(size_t)row * D + col] = make_float2(vx, vy);
            }
        }
    }
}

// ---------------- launch ----------------
extern "C" void kernel_launch(void* const* d_in, const int* in_sizes, int n_in,
                              void* d_out, int out_size) {
    const float* X     = (const float*)d_in[0];
    const int*   ntype = (const int*)d_in[1];
    const int*   ei    = (const int*)d_in[2];
    const int*   et    = (const int*)d_in[3];
    const float* aW    = (const float*)d_in[5];
    const float* ab    = (const float*)d_in[6];
    const float* Wrel  = (const float*)d_in[7];
    const float* Wself = (const float*)d_in[8];
    const float* bself = (const float*)d_in[9];
    float*       out   = (float*)d_out;

    int Nn = in_sizes[1];
    int E_ = in_sizes[3];

    void* ph2 = nullptr;
    cudaGetSymbolAddress(&ph2, g_h2);

    cudaFuncSetAttribute(gemm_layer_mma, cudaFuncAttributeMaxDynamicSharedMemorySize, G_SMEM);
    cudaFuncSetAttribute(adapt_mma,      cudaFuncAttributeMaxDynamicSharedMemorySize, ADA_SMEM);

    int nb = (Nn + 255) / 256;
    int eb = (E_ + 255) / 256;
    k_init   <<<nb, 256>>>(Nn);
    k_count  <<<eb, 256>>>(ei, E_);
    k_hist   <<<nb, 256>>>(ntype, Nn);
    k_inv    <<<nb, 256>>>(Nn);
    k_offs   <<<1, 1>>>();
    k_order  <<<nb, 256>>>(ntype, Nn);
    k_prefix <<<1, 1024>>>(Nn, E_);
    k_fillcsr<<<eb, 256>>>(ei, et, E_);
    k_packB  <<<(2 * 256 * KTOT + 255) / 256, 256>>>(Wrel, Wself);
    k_packWa <<<(NTYPE * D * DIN + 255) / 256, 256>>>(aW);
    k_convX  <<<(Nn * (DIN / 4) + 255) / 256, 256>>>(X, Nn);

    int ntilesM = (Nn + 127) / 128;
    adapt_mma<<<dim3(ntilesM, NTYPE), 256, ADA_SMEM>>>(ab, Nn);

    int aggBlk  = (Nn * 32 + 255) / 256;
    int convBlk = (Nn * (D / 4) + 255) / 256;
    for (int l = 0; l < 2; l++) {
        float* hout = (l == 0) ? (float*)ph2 : out;
        if (l == 1) k_convH<<<convBlk, 256>>>((const float*)ph2, Nn);
        k_aggregate<<<aggBlk, 256>>>(Nn);
        gemm_layer_mma<<<dim3(ntilesM, 2), 256, G_SMEM>>>(
            bself + (size_t)l * D, hout, Nn, l);
    }
}

// round 16
// speedup vs baseline: 1.0972x; 1.0972x over previous
#include <cuda_runtime.h>
#include <cuda_bf16.h>
#include <cuda_fp16.h>
#include <math.h>
#include <stdint.h>

#define NMAX   20000
#define EMAX   320000
#define DIN    512
#define D      256
#define NREL   6
#define NTYPE  8
#define KREL   (NREL * D)         // 1536
#define KTOT   (KREL + D)         // 1792
#define NCH64  (KTOT / 64)        // 28
#define NCHA   (DIN / 32)         // 16

// ---------------- scratch ----------------
__device__ float g_h  [NMAX * D];
__device__ float g_h2 [NMAX * D];
__device__ float g_inv[NMAX];
__device__ int   g_deg[NMAX];
__device__ int   g_cnt[NTYPE];
__device__ int   g_off[NTYPE + 1];
__device__ int   g_cur[NTYPE];
__device__ int   g_order[NMAX];
__device__ int   g_roff[NMAX + 1];
__device__ int   g_rcur[NMAX];
__device__ int   g_epack[EMAX];            // src*8 + rel
// A for layer GEMMs: single fp16 [m][KTOT]
__device__ __half g_Af[(size_t)NMAX * KTOT];
// B for layer GEMMs: single fp16 [layer][n][k]
__device__ __half g_Bf[2 * 256 * KTOT];
// adapt path: single fp16 X and W
__device__ __half g_Xf[(size_t)NMAX * DIN];
__device__ __half g_Waf[NTYPE * D * DIN];

// ---------------- helpers ----------------
__device__ __forceinline__ uint32_t smem_u32(const void* p) {
    uint32_t a;
    asm("{ .reg .u64 t; cvta.to.shared.u64 t, %1; cvt.u32.u64 %0, t; }" : "=r"(a) : "l"(p));
    return a;
}
__device__ __forceinline__ void mma_f16(float* c, const uint32_t* a, uint32_t b0, uint32_t b1) {
    asm volatile(
        "mma.sync.aligned.m16n8k16.row.col.f32.f16.f16.f32 "
        "{%0,%1,%2,%3}, {%4,%5,%6,%7}, {%8,%9}, {%0,%1,%2,%3};"
        : "+f"(c[0]), "+f"(c[1]), "+f"(c[2]), "+f"(c[3])
        : "r"(a[0]), "r"(a[1]), "r"(a[2]), "r"(a[3]), "r"(b0), "r"(b1));
}
__device__ __forceinline__ void ldsm4(uint32_t* r, uint32_t addr) {
    asm volatile("ldmatrix.sync.aligned.m8n8.x4.shared.b16 {%0,%1,%2,%3}, [%4];"
                 : "=r"(r[0]), "=r"(r[1]), "=r"(r[2]), "=r"(r[3]) : "r"(addr));
}
#define CP_ASYNC16(dst, src) \
    asm volatile("cp.async.cg.shared.global [%0], [%1], 16;" :: "r"(dst), "l"(src) : "memory")
#define CP_COMMIT()  asm volatile("cp.async.commit_group;" ::: "memory")
#define CP_WAIT1()   asm volatile("cp.async.wait_group 1;" ::: "memory")
#define CP_WAIT0()   asm volatile("cp.async.wait_group 0;" ::: "memory")

__device__ __forceinline__ uint32_t pack_h2(float x, float y) {
    __half2 h = __floats2half2_rn(x, y);
    return *reinterpret_cast<uint32_t*>(&h);
}

// ---------------- small prep kernels ----------------
__global__ void k_init(int Nn) {
    int i = blockIdx.x * 256 + threadIdx.x;
    if (i < Nn)    g_deg[i] = 0;
    if (i < NTYPE) g_cnt[i] = 0;
}
__global__ void k_count(const int* __restrict__ ei, int E_) {
    int e = blockIdx.x * 256 + threadIdx.x;
    if (e < E_) atomicAdd(&g_deg[ei[E_ + e]], 1);
}
__global__ void k_hist(const int* __restrict__ nt, int Nn) {
    int i = blockIdx.x * 256 + threadIdx.x;
    if (i < Nn) atomicAdd(&g_cnt[nt[i]], 1);
}
__global__ void k_inv(int Nn) {
    int i = blockIdx.x * 256 + threadIdx.x;
    if (i < Nn) g_inv[i] = 1.0f / fmaxf((float)g_deg[i], 1.0f);
}
__global__ void k_offs() {
    int s = 0;
    for (int t = 0; t < NTYPE; t++) { g_off[t] = s; g_cur[t] = s; s += g_cnt[t]; }
    g_off[NTYPE] = s;
}
__global__ void k_order(const int* __restrict__ nt, int Nn) {
    int i = blockIdx.x * 256 + threadIdx.x;
    if (i < Nn) {
        int pos = atomicAdd(&g_cur[nt[i]], 1);
        g_order[pos] = i;
    }
}
__global__ void k_prefix(int Nn, int E_) {
    __shared__ int sums[1024];
    int tid = threadIdx.x;
    int per = (Nn + 1023) / 1024;
    int base = tid * per;
    int s = 0;
    for (int i = 0; i < per; i++) {
        int idx = base + i;
        if (idx < Nn) s += g_deg[idx];
    }
    sums[tid] = s;
    __syncthreads();
    if (tid == 0) {
        int acc = 0;
        for (int i = 0; i < 1024; i++) { int t = sums[i]; sums[i] = acc; acc += t; }
    }
    __syncthreads();
    int run = sums[tid];
    for (int i = 0; i < per; i++) {
        int idx = base + i;
        if (idx < Nn) {
            g_roff[idx] = run;
            g_rcur[idx] = run;
            run += g_deg[idx];
        }
    }
    if (tid == 0) g_roff[Nn] = E_;
}
__global__ void k_fillcsr(const int* __restrict__ ei, const int* __restrict__ et, int E_) {
    int e = blockIdx.x * 256 + threadIdx.x;
    if (e >= E_) return;
    int dst = ei[E_ + e];
    int pos = atomicAdd(&g_rcur[dst], 1);
    g_epack[pos] = ei[e] * 8 + et[e];
}
// pack B single fp16, transposed to [l][e][k]
__global__ void k_packB(const float* __restrict__ Wrel, const float* __restrict__ Wself) {
    int idx = blockIdx.x * 256 + threadIdx.x;
    if (idx >= 2 * 256 * KTOT) return;
    int l    = idx / (256 * KTOT);
    int rest = idx % (256 * KTOT);
    int e    = rest / KTOT;
    int k    = rest % KTOT;
    float w;
    if (k < KREL) w = Wrel[(((size_t)l * NREL + (k >> 8)) * D + (k & 255)) * D + e];
    else          w = Wself[((size_t)l * D + (k - KREL)) * D + e];
    g_Bf[idx] = __float2half_rn(w);
}
__global__ void k_packWa(const float* __restrict__ W) {
    int idx = blockIdx.x * 256 + threadIdx.x;
    if (idx >= NTYPE * D * DIN) return;
    g_Waf[idx] = __float2half_rn(W[idx]);
}
__global__ void k_convX(const float* __restrict__ X, int Nn) {
    int i4 = blockIdx.x * 256 + threadIdx.x;
    if (i4 >= Nn * (DIN / 4)) return;
    int k = i4 * 4;
    float4 v = *(const float4*)&X[(size_t)k];
    *(uint2*)&g_Xf[(size_t)k] = make_uint2(pack_h2(v.x, v.y), pack_h2(v.z, v.w));
}
// h fp32 -> fp16 into h-part of A (race-free: own launch)
__global__ void k_convH(const float* __restrict__ hin, int Nn) {
    int i = blockIdx.x * 256 + threadIdx.x;
    if (i >= Nn * (D / 4)) return;
    int m = i >> 6;
    int k = (i & 63) * 4;
    float4 v = *(const float4*)&hin[(size_t)m * D + k];
    size_t off = (size_t)m * KTOT + KREL + k;
    *(uint2*)&g_Af[off] = make_uint2(pack_h2(v.x, v.y), pack_h2(v.z, v.w));
}

// ---------------- CSR gather-aggregate (fp32 h gathers, proven) --------------
__global__ void k_aggregate(const float* __restrict__ hin, int Nn) {
    int gw   = (blockIdx.x * blockDim.x + threadIdx.x) >> 5;
    int lane = threadIdx.x & 31;
    if (gw >= Nn) return;
    int start = g_roff[gw], end = g_roff[gw + 1];
    float acc[NREL][8];
#pragma unroll
    for (int r = 0; r < NREL; r++)
#pragma unroll
        for (int j = 0; j < 8; j++) acc[r][j] = 0.f;

    for (int i = start; i < end; i++) {
        int p = g_epack[i];
        int s = p >> 3, r = p & 7;
        const float4* hp = (const float4*)(hin + (size_t)s * D + lane * 8);
        float4 v0 = hp[0], v1 = hp[1];
        float v[8] = {v0.x, v0.y, v0.z, v0.w, v1.x, v1.y, v1.z, v1.w};
#pragma unroll
        for (int rr = 0; rr < NREL; rr++) {
            if (rr == r) {
#pragma unroll
                for (int j = 0; j < 8; j++) acc[rr][j] += v[j];
            }
        }
    }
    float s = g_inv[gw];
#pragma unroll
    for (int r = 0; r < NREL; r++) {
        uint32_t hw[4];
#pragma unroll
        for (int q = 0; q < 4; q++)
            hw[q] = pack_h2(acc[r][2 * q] * s, acc[r][2 * q + 1] * s);
        size_t off = (size_t)gw * KTOT + r * D + lane * 8;
        *(uint4*)&g_Af[off] = make_uint4(hw[0], hw[1], hw[2], hw[3]);
    }
}

// ---------------- adapt GEMM via mma: single-product f16 (proven) ------------
#define ADA_A  0
#define ADA_B  10240
#define ADA_BUF 30720
#define ADA_SMEM (2 * ADA_BUF)   // 61440

__global__ __launch_bounds__(256, 2)
void adapt_mma(const float* __restrict__ bias, int Nn) {
    extern __shared__ char smem[];
    __shared__ int nid_s[128];
    uint32_t sb = smem_u32(smem);
    int t    = blockIdx.y;
    int base = g_off[t];
    int cntv = g_off[t + 1] - base;
    int m0   = blockIdx.x * 128;
    if (m0 >= cntv) return;

    int tid  = threadIdx.x;
    int wid  = tid >> 5;
    int lane = tid & 31;
    int wm   = wid & 3;
    int wn   = wid >> 2;

    if (tid < 128) {
        int idx = m0 + tid;
        nid_s[tid] = (idx < cntv) ? g_order[base + idx] : g_order[base];
    }
    __syncthreads();

    const __half* Wf = g_Waf + (size_t)t * D * DIN;

    float acc[2][16][4];
#pragma unroll
    for (int i = 0; i < 2; i++)
#pragma unroll
        for (int j = 0; j < 16; j++)
#pragma unroll
            for (int q = 0; q < 4; q++) acc[i][j][q] = 0.f;

    auto load_chunk = [&](int c, int p) {
        int k0 = c * 32;
        uint32_t dstb = sb + p * ADA_BUF;
#pragma unroll
        for (int i = 0; i < 6; i++) {
            int sid = tid + i * 256;
            const __half* srcp;
            uint32_t dst;
            if (sid < 512) {
                int row = sid >> 2, seg = sid & 3;
                srcp = g_Xf + (size_t)nid_s[row] * DIN + k0 + seg * 8;
                dst  = dstb + ADA_A + row * 80 + seg * 16;
            } else {
                int t2 = sid - 512;
                int row = t2 >> 2, seg = t2 & 3;
                srcp = Wf + (size_t)row * DIN + k0 + seg * 8;
                dst  = dstb + ADA_B + row * 80 + seg * 16;
            }
            CP_ASYNC16(dst, srcp);
        }
        CP_COMMIT();
    };

    load_chunk(0, 0);
    for (int c = 0; c < NCHA; c++) {
        int p = c & 1;
        if (c + 1 < NCHA) { load_chunk(c + 1, p ^ 1); CP_WAIT1(); }
        else              { CP_WAIT0(); }
        __syncthreads();
        uint32_t bufb = sb + p * ADA_BUF;
#pragma unroll
        for (int ks = 0; ks < 2; ks++) {
            uint32_t ah[2][4];
            int arow = wm * 32 + (lane & 15);
            uint32_t acol = ((uint32_t)((lane >> 4) * 8 + ks * 16)) * 2;
#pragma unroll
            for (int mt = 0; mt < 2; mt++)
                ldsm4(ah[mt], bufb + ADA_A + (arow + mt * 16) * 80 + acol);
            int brow0 = wn * 128 + ((lane >> 4) * 8) + (lane & 7);
            uint32_t bkoff = ((uint32_t)(ks * 16 + ((lane >> 3) & 1) * 8)) * 2;
#pragma unroll
            for (int np = 0; np < 8; np++) {
                uint32_t bh[4];
                ldsm4(bh, bufb + ADA_B + (brow0 + np * 16) * 80 + bkoff);
#pragma unroll
                for (int mt = 0; mt < 2; mt++) {
                    mma_f16(acc[mt][np * 2],     ah[mt], bh[0], bh[1]);
                    mma_f16(acc[mt][np * 2 + 1], ah[mt], bh[2], bh[3]);
                }
            }
        }
        __syncthreads();
    }

    // epilogue: tanh + bias; write g_h fp32 and fp16 h-part of A
    int g   = lane >> 2;
    int tig = lane & 3;
#pragma unroll
    for (int mt = 0; mt < 2; mt++) {
        int lr0 = wm * 32 + mt * 16 + g;
#pragma unroll
        for (int half = 0; half < 2; half++) {
            int lr = lr0 + half * 8;
            if (m0 + lr >= cntv) continue;
            int node = nid_s[lr];
#pragma unroll
            for (int nt = 0; nt < 16; nt++) {
                int col = wn * 128 + nt * 8 + tig * 2;
                float vx = tanhf(acc[mt][nt][half * 2]     + bias[t * D + col]);
                float vy = tanhf(acc[mt][nt][half * 2 + 1] + bias[t * D + col + 1]);
                *(float2*)&g_h[(size_t)node * D + col] = make_float2(vx, vy);
                *(uint32_t*)&g_Af[(size_t)node * KTOT + KREL + col] = pack_h2(vx, vy);
            }
        }
    }
}

// ---------------- fused layer GEMM: f16, 128x128, K-chunk 64, 2 CTAs/SM ------
// SMEM row pitch 144B (64 els + 8 pad): bank stride 36 mod 32 = 4 -> the 8
// ldmatrix rows cover all 32 banks, conflict-free.
#define G_A   0
#define G_B   18432
#define G_BUF 36864
#define G_SMEM (2 * G_BUF)    // 73728

__global__ __launch_bounds__(256, 2)
void gemm_layer_mma(const float* __restrict__ bself, float* __restrict__ hout,
                    int Nn, int layer) {
    extern __shared__ char smem[];
    uint32_t sb = smem_u32(smem);
    int tid  = threadIdx.x;
    int wid  = tid >> 5;
    int lane = tid & 31;
    int wm   = wid & 3;            // 4 warp rows x 32
    int wn   = wid >> 2;           // 2 warp cols x 64
    int m0   = blockIdx.x * 128;
    int n0   = blockIdx.y * 128;

    const __half* B_g = g_Bf + (size_t)layer * 256 * KTOT + (size_t)n0 * KTOT;

    float acc[2][8][4];
#pragma unroll
    for (int i = 0; i < 2; i++)
#pragma unroll
        for (int j = 0; j < 8; j++)
#pragma unroll
            for (int q = 0; q < 4; q++) acc[i][j][q] = 0.f;

    // 2048 16B segments per chunk: A 1024 (128 rows x 8), B 1024 -> 8/thread
    auto load_chunk = [&](int c, int p) {
        int k0 = c * 64;
        uint32_t dstb = sb + p * G_BUF;
#pragma unroll
        for (int i = 0; i < 8; i++) {
            int sid = tid + i * 256;
            int arr = sid >> 10;           // 0:A 1:B
            int s   = sid & 1023;
            int row = s >> 3;
            int seg = s & 7;
            const __half* srcp;
            if (arr == 0) {
                int grow = m0 + row; if (grow > Nn - 1) grow = Nn - 1;
                srcp = g_Af + (size_t)grow * KTOT + k0 + seg * 8;
            } else {
                srcp = B_g + (size_t)row * KTOT + k0 + seg * 8;
            }
            CP_ASYNC16(dstb + arr * 18432 + row * 144 + seg * 16, srcp);
        }
        CP_COMMIT();
    };

    load_chunk(0, 0);
    for (int c = 0; c < NCH64; c++) {
        int p = c & 1;
        if (c + 1 < NCH64) { load_chunk(c + 1, p ^ 1); CP_WAIT1(); }
        else               { CP_WAIT0(); }
        __syncthreads();
        uint32_t bufb = sb + p * G_BUF;
#pragma unroll
        for (int ks = 0; ks < 4; ks++) {
            uint32_t ah[2][4];
            int arow = wm * 32 + (lane & 15);
            uint32_t acol = ((uint32_t)((lane >> 4) * 8 + ks * 16)) * 2;
#pragma unroll
            for (int mt = 0; mt < 2; mt++)
                ldsm4(ah[mt], bufb + G_A + (arow + mt * 16) * 144 + acol);
            int brow0 = wn * 64 + ((lane >> 4) * 8) + (lane & 7);
            uint32_t bkoff = ((uint32_t)(ks * 16 + ((lane >> 3) & 1) * 8)) * 2;
#pragma unroll
            for (int np = 0; np < 4; np++) {
                uint32_t bh[4];
                ldsm4(bh, bufb + G_B + (brow0 + np * 16) * 144 + bkoff);
#pragma unroll
                for (int mt = 0; mt < 2; mt++) {
                    mma_f16(acc[mt][np * 2],     ah[mt], bh[0], bh[1]);
                    mma_f16(acc[mt][np * 2 + 1], ah[mt], bh[2], bh[3]);
                }
            }
        }
        __syncthreads();
    }

    // epilogue: bias + relu
    int g   = lane >> 2;
    int tig = lane & 3;
#pragma unroll
    for (int mt = 0; mt < 2; mt++) {
        int row0 = m0 + wm * 32 + mt * 16 + g;
#pragma unroll
        for (int half = 0; half < 2; half++) {
            int row = row0 + half * 8;
            if (row >= Nn) continue;
#pragma unroll
            for (int nt = 0; nt < 8; nt++) {
                int col = n0 + wn * 64 + nt * 8 + tig * 2;
                float vx = fmaxf(acc[mt][nt][half * 2]     + bself[col], 0.f);
                float vy = fmaxf(acc[mt][nt][half * 2 + 1] + bself[col + 1], 0.f);
                *(float2*)&hout[(size_t)row * D + col] = make_float2(vx, vy);
            }
        }
    }
}

// ---------------- launch ----------------
extern "C" void kernel_launch(void* const* d_in, const int* in_sizes, int n_in,
                              void* d_out, int out_size) {
    const float* X     = (const float*)d_in[0];
    const int*   ntype = (const int*)d_in[1];
    const int*   ei    = (const int*)d_in[2];
    const int*   et    = (const int*)d_in[3];
    const float* aW    = (const float*)d_in[5];
    const float* ab    = (const float*)d_in[6];
    const float* Wrel  = (const float*)d_in[7];
    const float* Wself = (const float*)d_in[8];
    const float* bself = (const float*)d_in[9];
    float*       out   = (float*)d_out;

    int Nn = in_sizes[1];
    int E_ = in_sizes[3];

    void *ph = nullptr, *ph2 = nullptr;
    cudaGetSymbolAddress(&ph,  g_h);
    cudaGetSymbolAddress(&ph2, g_h2);

    cudaFuncSetAttribute(gemm_layer_mma, cudaFuncAttributeMaxDynamicSharedMemorySize, G_SMEM);
    cudaFuncSetAttribute(adapt_mma,      cudaFuncAttributeMaxDynamicSharedMemorySize, ADA_SMEM);

    int nb = (Nn + 255) / 256;
    int eb = (E_ + 255) / 256;
    k_init   <<<nb, 256>>>(Nn);
    k_count  <<<eb, 256>>>(ei, E_);
    k_hist   <<<nb, 256>>>(ntype, Nn);
    k_inv    <<<nb, 256>>>(Nn);
    k_offs   <<<1, 1>>>();
    k_order  <<<nb, 256>>>(ntype, Nn);
    k_prefix <<<1, 1024>>>(Nn, E_);
    k_fillcsr<<<eb, 256>>>(ei, et, E_);
    k_packB  <<<(2 * 256 * KTOT + 255) / 256, 256>>>(Wrel, Wself);
    k_packWa <<<(NTYPE * D * DIN + 255) / 256, 256>>>(aW);
    k_convX  <<<(Nn * (DIN / 4) + 255) / 256, 256>>>(X, Nn);

    int ntilesM = (Nn + 127) / 128;
    adapt_mma<<<dim3(ntilesM, NTYPE), 256, ADA_SMEM>>>(ab, Nn);

    int aggBlk  = (Nn * 32 + 255) / 256;
    int convBlk = (Nn * (D / 4) + 255) / 256;
    for (int l = 0; l < 2; l++) {
        const float* hin  = (l == 0) ? (const float*)ph : (const float*)ph2;
        float*       hout = (l == 0) ? (float*)ph2 : out;
        if (l == 1) k_convH<<<convBlk, 256>>>(hin, Nn);
        k_aggregate<<<aggBlk, 256>>>(hin, Nn);
        gemm_layer_mma<<<dim3(ntilesM, 2), 256, G_SMEM>>>(
            bself + (size_t)l * D, hout, Nn, l);
    }
}